// round 13
// baseline (speedup 1.0000x reference)
#include <cuda_runtime.h>
#include <cuda_bf16.h>
#include <cstdint>

// ChannelPruner: out[b,o,h,w] = sum_c w[o,c] * x[b,c,h,w]
// x: (32, 256, 56, 56) fp32; w: (256,256,1,1) fp32, sparse rows discovered at
// runtime (correct for ANY w).
//
// R13: software-pipelined apply. 888 blocks (148x6 resident) iterate over
// planes with stride 888. Per iteration, steady state overlaps:
//   cp.async.cg prefetch of plane i+1 (no dest regs -> issued before waiting)
//   FMA on plane i from smem
//   TMA bulk store of plane i-1 draining to DRAM
// CSR metadata from a ~0.3us pre-kernel. Double-buffered 25KB smem.

#define N_CH        256
#define BATCH       32
#define HW4         784                   // (56*56)/4 float4 per plane
#define BSTRIDE     (N_CH * HW4)
#define NPLANE      (BATCH * N_CH)        // 8192
#define NBLK        888                   // 148 SMs x 6 blocks
#define PLANE_BYTES (HW4 * 16)            // 12544 B

__device__ int   g_nnz[N_CH];
__device__ int   g_cols[N_CH * N_CH];
__device__ float g_vals[N_CH * N_CH];

// ---------------------------------------------------------------------------
// Kernel 1: one warp per weight row, compact nonzeros via warp scan. (~0.3us)
// ---------------------------------------------------------------------------
__global__ __launch_bounds__(256) void build_csr(const float* __restrict__ w) {
    const int row  = blockIdx.x * 8 + (threadIdx.x >> 5);
    const int lane = threadIdx.x & 31;
    const float* wr = w + row * N_CH;

    float v[8];
    int cnt = 0;
    const int base = lane * 8;
#pragma unroll
    for (int k = 0; k < 8; k++) {
        v[k] = wr[base + k];
        if (v[k] != 0.0f) cnt++;
    }
    int scan = cnt;
#pragma unroll
    for (int d = 1; d < 32; d <<= 1) {
        int t = __shfl_up_sync(0xffffffffu, scan, d);
        if (lane >= d) scan += t;
    }
    const int total = __shfl_sync(0xffffffffu, scan, 31);
    int p = row * N_CH + (scan - cnt);
#pragma unroll
    for (int k = 0; k < 8; k++) {
        if (v[k] != 0.0f) { g_cols[p] = base + k; g_vals[p] = v[k]; p++; }
    }
    if (lane == 31) g_nnz[row] = total;
}

// ---------------------------------------------------------------------------
__device__ __forceinline__ uint32_t smem_u32(const void* p) {
    uint32_t a;
    asm("{ .reg .u64 t; cvta.to.shared.u64 t, %1; cvt.u32.u64 %0, t; }"
        : "=r"(a) : "l"(p));
    return a;
}

__device__ __forceinline__ void cp16(uint32_t dst, const float4* src) {
    asm volatile("cp.async.cg.shared.global [%0], [%1], 16;"
                 :: "r"(dst), "l"(src) : "memory");
}

// ---------------------------------------------------------------------------
// Kernel 2: pipelined apply.
// ---------------------------------------------------------------------------
__global__ __launch_bounds__(256, 6) void apply_pipe(const float4* __restrict__ x,
                                                     float4* __restrict__ out) {
    __shared__ alignas(128) float4 s_in[2][HW4];   // 2 x 12544 B

    const int  tid  = threadIdx.x;
    const bool tail = tid < (HW4 - 768);           // tid < 16
    const int  n_iter = (NPLANE - (int)blockIdx.x + NBLK - 1) / NBLK;

    const uint32_t sb0 = smem_u32(&s_in[0][0]);
    const uint32_t sb1 = smem_u32(&s_in[1][0]);

    // ---- metadata + prefetch for iteration 0 ----
    int   bo  = blockIdx.x;
    int   o   = bo & (N_CH - 1);
    int   nnz = __ldg(&g_nnz[o]);
    float v0  = 0.f;
    if (nnz > 0) {
        const int c0 = __ldg(&g_cols[o * N_CH]);
        v0 = __ldg(&g_vals[o * N_CH]);
        const float4* src = x + (size_t)(bo >> 8) * BSTRIDE + (size_t)c0 * HW4 + tid;
        const uint32_t d = sb0 + tid * 16;
        cp16(d,         src);
        cp16(d + 4096,  src + 256);
        cp16(d + 8192,  src + 512);
        if (tail) cp16(d + 12288, src + 768);
    }
    asm volatile("cp.async.commit_group;" ::: "memory");

    for (int i = 0; i < n_iter; i++) {
        const int   s       = i & 1;
        const int   cur_bo  = bo;
        const int   cur_o   = o;
        const int   cur_nnz = nnz;
        const float cur_v0  = v0;
        const uint32_t sbuf = s ? sb1 : sb0;

        // [A] this iteration's cp.async group complete
        asm volatile("cp.async.wait_group 0;" ::: "memory");
        // [B] TMA store that read buffer s^1 (iter i-1) finished its smem read
        if (tid == 0)
            asm volatile("cp.async.bulk.wait_group.read 0;" ::: "memory");
        // [C] publish both to all threads
        __syncthreads();

        // [D] compute
        float4 z = make_float4(0.f, 0.f, 0.f, 0.f);
        float4 a0 = z, a1 = z, a2 = z, a3 = z;
        if (cur_nnz > 0) {
            const float4 r0 = s_in[s][tid];
            const float4 r1 = s_in[s][tid + 256];
            const float4 r2 = s_in[s][tid + 512];
            a0.x = cur_v0 * r0.x; a0.y = cur_v0 * r0.y; a0.z = cur_v0 * r0.z; a0.w = cur_v0 * r0.w;
            a1.x = cur_v0 * r1.x; a1.y = cur_v0 * r1.y; a1.z = cur_v0 * r1.z; a1.w = cur_v0 * r1.w;
            a2.x = cur_v0 * r2.x; a2.y = cur_v0 * r2.y; a2.z = cur_v0 * r2.z; a2.w = cur_v0 * r2.w;
            if (tail) {
                const float4 r3 = s_in[s][tid + 768];
                a3.x = cur_v0 * r3.x; a3.y = cur_v0 * r3.y; a3.z = cur_v0 * r3.z; a3.w = cur_v0 * r3.w;
            }
            // general path: remaining nonzeros via direct MLP-4 LDG (rare)
#pragma unroll 1
            for (int j = 1; j < cur_nnz; j++) {
                const int   c = __ldg(&g_cols[cur_o * N_CH + j]);
                const float v = __ldg(&g_vals[cur_o * N_CH + j]);
                const float4* xc = x + (size_t)(cur_bo >> 8) * BSTRIDE
                                     + (size_t)c * HW4 + tid;
                const float4 q0 = __ldg(xc);
                const float4 q1 = __ldg(xc + 256);
                const float4 q2 = __ldg(xc + 512);
                a0.x += v * q0.x; a0.y += v * q0.y; a0.z += v * q0.z; a0.w += v * q0.w;
                a1.x += v * q1.x; a1.y += v * q1.y; a1.z += v * q1.z; a1.w += v * q1.w;
                a2.x += v * q2.x; a2.y += v * q2.y; a2.z += v * q2.z; a2.w += v * q2.w;
                if (tail) {
                    const float4 q3 = __ldg(xc + 768);
                    a3.x += v * q3.x; a3.y += v * q3.y; a3.z += v * q3.z; a3.w += v * q3.w;
                }
            }
        }

        // [E] prefetch iteration i+1 into buffer s^1 (safe per [B]+[C])
        if (i + 1 < n_iter) {
            bo += NBLK;
            o   = bo & (N_CH - 1);
            nnz = __ldg(&g_nnz[o]);
            if (nnz > 0) {
                const int c0 = __ldg(&g_cols[o * N_CH]);
                v0 = __ldg(&g_vals[o * N_CH]);
                const float4* src = x + (size_t)(bo >> 8) * BSTRIDE
                                      + (size_t)c0 * HW4 + tid;
                const uint32_t d = (s ? sb0 : sb1) + tid * 16;
                cp16(d,         src);
                cp16(d + 4096,  src + 256);
                cp16(d + 8192,  src + 512);
                if (tail) cp16(d + 12288, src + 768);
            }
            asm volatile("cp.async.commit_group;" ::: "memory");
        }

        // [F] results into buffer s (thread-private slots, overwrite in place)
        s_in[s][tid]       = a0;
        s_in[s][tid + 256] = a1;
        s_in[s][tid + 512] = a2;
        if (tail) s_in[s][tid + 768] = a3;
        // [G] all STS visible
        __syncthreads();
        // [H] TMA bulk store of the finished plane
        if (tid == 0) {
            asm volatile("fence.proxy.async.shared::cta;" ::: "memory");
            float4* dst = out + (size_t)cur_bo * HW4;
            asm volatile(
                "cp.async.bulk.global.shared::cta.bulk_group [%0], [%1], %2;"
                :: "l"(dst), "r"(sbuf), "r"((uint32_t)PLANE_BYTES) : "memory");
            asm volatile("cp.async.bulk.commit_group;" ::: "memory");
        }
    }

    // smem must not be reallocated while the last TMA store is still reading
    if (tid == 0)
        asm volatile("cp.async.bulk.wait_group.read 0;" ::: "memory");
}

extern "C" void kernel_launch(void* const* d_in, const int* in_sizes, int n_in,
                              void* d_out, int out_size) {
    const float4* x = (const float4*)d_in[0];
    const float*  w = (const float*)d_in[1];
    float4* out = (float4*)d_out;

    build_csr<<<32, 256>>>(w);
    apply_pipe<<<NBLK, 256>>>(x, out);
}

// round 15
// speedup vs baseline: 1.0589x; 1.0589x over previous
#include <cuda_runtime.h>
#include <cuda_bf16.h>
#include <cstdint>

// ChannelPruner: out[b,o,h,w] = sum_c w[o,c] * x[b,c,h,w]
// x: (32, 256, 56, 56) fp32; w: (256,256,1,1) fp32, sparse rows discovered at
// runtime (correct for ANY w).
//
// R14 = R10 (fused, MLP-4 LDG body, smem-staged TMA bulk store) at HALF-plane
// granularity: 16384 blocks x 128 threads. Same 64-warp/SM budget, but 16
// independent plane-phases in flight per SM instead of 8 -> finer interleave
// of load bursts and TMA stores at the DRAM controllers.

#define N_CH       256
#define BATCH      32
#define HW4        784                    // (56*56)/4 float4 per plane
#define HHW4       392                    // half plane in float4
#define HALF_BYTES (HHW4 * 16)            // 6272 B
#define NBLK       (BATCH * N_CH * 2)     // 16384 half-plane blocks

__device__ __forceinline__ uint32_t smem_u32(const void* p) {
    uint32_t a;
    asm("{ .reg .u64 t; cvta.to.shared.u64 t, %1; cvt.u32.u64 %0, t; }"
        : "=r"(a) : "l"(p));
    return a;
}

__global__ __launch_bounds__(128, 16) void prune_fused(const float4* __restrict__ x,
                                                       const float*  __restrict__ w,
                                                       float4* __restrict__ out) {
    __shared__ alignas(128) float4 s_out[HHW4];   // 6272 B staging
    __shared__ int   s_cols[N_CH];
    __shared__ float s_vals[N_CH];
    __shared__ int   s_warp_off[5];

    const int tid  = threadIdx.x;
    const int lane = tid & 31;
    const int wid  = tid >> 5;               // 0..3

    const int bo   = blockIdx.x >> 1;        // plane index b*256 + o
    const int half = blockIdx.x & 1;         // which half of the plane
    const int o    = bo & (N_CH - 1);

    // ---- prologue: compaction of w row o (128 thr, 2 values each) ----
    const float wv0 = __ldg(&w[o * N_CH + tid]);
    const float wv1 = __ldg(&w[o * N_CH + 128 + tid]);
    int cnt = (wv0 != 0.0f) + (wv1 != 0.0f);

    int scan = cnt;                          // inclusive warp scan
#pragma unroll
    for (int d = 1; d < 32; d <<= 1) {
        int t = __shfl_up_sync(0xffffffffu, scan, d);
        if (lane >= d) scan += t;
    }
    if (lane == 31) s_warp_off[wid + 1] = scan;
    __syncthreads();
    if (tid == 0) {
        int acc = 0;
        s_warp_off[0] = 0;
#pragma unroll
        for (int i = 0; i < 4; i++) { acc += s_warp_off[i + 1]; s_warp_off[i + 1] = acc; }
    }
    __syncthreads();
    {
        int p = s_warp_off[wid] + (scan - cnt);   // exclusive offset
        if (wv0 != 0.0f) { s_cols[p] = tid;       s_vals[p] = wv0; p++; }
        if (wv1 != 0.0f) { s_cols[p] = tid + 128; s_vals[p] = wv1; }
    }
    __syncthreads();

    const int nnz = s_warp_off[4];

    // ---- body: 392 float4 over 128 threads = 3/thread + 8-thread tail ----
    float4 z = make_float4(0.f, 0.f, 0.f, 0.f);
    float4 a0 = z, a1 = z, a2 = z, a3 = z;

    const float4* xb = x + (size_t)(bo >> 8) * (N_CH * HW4) + half * HHW4;
    const bool tail = tid < (HHW4 - 384);    // tid < 8

    for (int j = 0; j < nnz; j++) {
        const int   c = s_cols[j];
        const float v = s_vals[j];
        const float4* xc = xb + (size_t)c * HW4 + tid;
        // 4 independent LDG.128 (MLP=4) before any FMA
        const float4 r0 = __ldg(xc);
        const float4 r1 = __ldg(xc + 128);
        const float4 r2 = __ldg(xc + 256);
        float4 r3 = z;
        if (tail) r3 = __ldg(xc + 384);

        a0.x += v * r0.x; a0.y += v * r0.y; a0.z += v * r0.z; a0.w += v * r0.w;
        a1.x += v * r1.x; a1.y += v * r1.y; a1.z += v * r1.z; a1.w += v * r1.w;
        a2.x += v * r2.x; a2.y += v * r2.y; a2.z += v * r2.z; a2.w += v * r2.w;
        if (tail) {
            a3.x += v * r3.x; a3.y += v * r3.y; a3.z += v * r3.z; a3.w += v * r3.w;
        }
    }

    // ---- epilogue: stage to smem, one 6272B TMA bulk store ----
    s_out[tid]       = a0;
    s_out[tid + 128] = a1;
    s_out[tid + 256] = a2;
    if (tail) s_out[tid + 384] = a3;
    __syncthreads();

    if (tid == 0) {
        asm volatile("fence.proxy.async.shared::cta;" ::: "memory");
        const uint32_t src = smem_u32(s_out);
        float4* dst = out + (size_t)bo * HW4 + half * HHW4;
        asm volatile(
            "cp.async.bulk.global.shared::cta.bulk_group [%0], [%1], %2;"
            :: "l"(dst), "r"(src), "r"((uint32_t)HALF_BYTES) : "memory");
        asm volatile("cp.async.bulk.commit_group;" ::: "memory");
        asm volatile("cp.async.bulk.wait_group.read 0;" ::: "memory");
    }
}

extern "C" void kernel_launch(void* const* d_in, const int* in_sizes, int n_in,
                              void* d_out, int out_size) {
    const float4* x = (const float4*)d_in[0];
    const float*  w = (const float*)d_in[1];
    float4* out = (float4*)d_out;

    prune_fused<<<NBLK, 128>>>(x, w, out);
}